// round 14
// baseline (speedup 1.0000x reference)
#include <cuda_runtime.h>
#include <cstdint>

static constexpr int K_TOTAL = 1280, N_TOTAL = 1280;
static constexpr int BM = 128, BN = 128;
static constexpr int SLICES = 40;
static constexpr int NTILES = 10, MTILES = 512;
static constexpr int GRID = NTILES * MTILES;   // 5120
static constexpr int THREADS = 256;
static constexpr int STAGES = 3;

static constexpr int A_STG = 18432;   // 128 rows * 144B
static constexpr int B_STG = 16384;   // 4096 floats
static constexpr int B2_STG = 1024;
static constexpr int OFF_A = 0;                    // 3*18432 = 55296
static constexpr int OFF_B = 55296;                // 3*16384 = 49152
static constexpr int OFF_B2 = 104448;              // 3*1024  = 3072
static constexpr int OFF_BAR = 107520;             // 3 mbarriers
static constexpr int SMEM_BYTES = 107584;
// epilogue aliases (A-stage space is dead after the mainloop)
static constexpr int OFF_WU = 0;                   // 2048 B
static constexpr int OFF_DN = 2048;                // 4 * 2048 B
static constexpr unsigned TX_BYTES = 16384u + 16384u + 1024u;  // A + B + B2

// W fragments, per 32-k slice block of 4096 floats:
// (((pair*4+ks)*32 + gid*4 + tig)*4 + nfo*2 + kh), pair = n16-group 0..7
__device__ __align__(16) float g_Wfrag[NTILES * SLICES * 4096];
// Wd fragments: [lora][slice32][(ks*32+lane)*2 + kh]
__device__ __align__(16) float g_Wdfrag[50 * SLICES * 256];

__device__ __forceinline__ uint32_t smem_u32(const void* p) {
    uint32_t a;
    asm("{ .reg .u64 t; cvta.to.shared.u64 t, %1; cvt.u32.u64 %0, t; }" : "=r"(a) : "l"(p));
    return a;
}
__device__ __forceinline__ uint32_t rna(float f) {
    uint32_t b;
    asm("cvt.rna.tf32.f32 %0, %1;" : "=r"(b) : "f"(f));
    return b;
}
__device__ __forceinline__ void mma8(float* c, const uint32_t* a, uint32_t b0, uint32_t b1) {
    asm volatile(
        "mma.sync.aligned.m16n8k8.row.col.f32.tf32.tf32.f32 "
        "{%0,%1,%2,%3}, {%4,%5,%6,%7}, {%8,%9}, {%0,%1,%2,%3};"
        : "+f"(c[0]), "+f"(c[1]), "+f"(c[2]), "+f"(c[3])
        : "r"(a[0]), "r"(a[1]), "r"(a[2]), "r"(a[3]), "r"(b0), "r"(b1));
}
__device__ __forceinline__ void bulk_cp(uint32_t dst, const void* src, uint32_t bytes, uint32_t mb) {
    asm volatile(
        "cp.async.bulk.shared::cta.global.mbarrier::complete_tx::bytes [%0], [%1], %2, [%3];"
        :: "r"(dst), "l"(src), "r"(bytes), "r"(mb) : "memory");
}
#define MBAR_INIT(a, c) \
    asm volatile("mbarrier.init.shared.b64 [%0], %1;" :: "r"((uint32_t)(a)), "r"((uint32_t)(c)) : "memory")
#define MBAR_EXPECT(a, tx) \
    asm volatile("mbarrier.arrive.expect_tx.shared.b64 _, [%0], %1;" :: "r"((uint32_t)(a)), "r"((uint32_t)(tx)) : "memory")
#define MBAR_WAIT(a, ph) do { \
    uint32_t _m = (uint32_t)(a), _p = (uint32_t)(ph), _d; \
    asm volatile("{ .reg .pred p; mbarrier.try_wait.parity.acquire.cta.shared::cta.b64 p, [%1], %2; selp.b32 %0, 1, 0, p; }" \
        : "=r"(_d) : "r"(_m), "r"(_p) : "memory"); \
    if (!_d) { \
        asm volatile("{ .reg .pred P1;\nWL_%=: mbarrier.try_wait.parity.acquire.cta.shared::cta.b64 P1, [%0], %1, 0x989680;\n@P1 bra.uni WD_%=;\nbra.uni WL_%=;\nWD_%=: }" \
            :: "r"(_m), "r"(_p) : "memory"); \
    } \
} while (0)

// ---------------- prepass
__global__ void prep_kernel(const float* __restrict__ W, const float* __restrict__ Wd) {
    int i = blockIdx.x * blockDim.x + threadIdx.x;
    const int NW = N_TOTAL * K_TOTAL;
    if (i < NW) {
        int n = i / K_TOTAL, k = i % K_TOTAL;
        int ntile = n >> 7, nn = n & 127;
        int pair = nn >> 4, nfo = (nn >> 3) & 1, gid = nn & 7;
        int slice = k >> 5, ks = (k >> 3) & 3, kh = (k >> 2) & 1, tig = k & 3;
        int off = (ntile * SLICES + slice) * 4096 +
                  (((pair * 4 + ks) * 32 + gid * 4 + tig) * 4 + nfo * 2 + kh);
        g_Wfrag[off] = __uint_as_float(rna(W[i]));
    } else if (i < NW + 50 * K_TOTAL * 8) {
        int j = i - NW;
        int gid = j & 7, t = j >> 3, k = t % K_TOTAL, l = t / K_TOTAL;
        float v = 0.f;
        if (gid < 4) v = __uint_as_float(rna(Wd[(l * 4 + gid) * K_TOTAL + k]));
        int slice = k >> 5, ks = (k >> 3) & 3, kh = (k >> 2) & 1, tig = k & 3;
        g_Wdfrag[(l * SLICES + slice) * 256 + (ks * 32 + gid * 4 + tig) * 2 + kh] = v;
    }
}

// ---------------- main fused kernel: 256 threads, 2 CTAs/SM, bulk-async fed
__global__ void __launch_bounds__(THREADS, 2)
lora_gemm(const float* __restrict__ x, const int* __restrict__ lora_id,
          const float* __restrict__ Wu, float* __restrict__ out) {
    extern __shared__ char smem[];
    const uint32_t sb = smem_u32(smem);
    const int tid = threadIdx.x, lane = tid & 31, wid = tid >> 5;
    const int bid = blockIdx.x;
    const int ntile = bid % NTILES, mtile = bid / NTILES;
    const int m0 = mtile * BM, nb = ntile * BN;

    const int id = lora_id[m0 >> 12];
    const int idx = (id >= 0) ? ((id >> 2) > 49 ? 49 : (id >> 2)) : 0;
    const float coeff = (id >= 0) ? 1.f : 0.f;

    // carry Wu tile (128n x 4r fp32 = 128 float4) in registers until epilogue
    float4 wuv = make_float4(0.f, 0.f, 0.f, 0.f);
    if (tid < 128)
        wuv = ((const float4*)Wu)[(size_t)idx * N_TOTAL + nb + tid];

    const int gid = lane >> 2, tig = lane & 3;
    const int wr = wid >> 2, wc = wid & 3;   // 2 x 4 warp grid, warp tile 64x32

    const float* wsrc = g_Wfrag + (size_t)ntile * SLICES * 4096;
    const float* wdsrc = g_Wdfrag + (size_t)idx * SLICES * 256;

    const uint32_t abase0 = sb + OFF_A + (wr * 64 + (lane & 15)) * 144 + (lane >> 4) * 16;
    const uint32_t bcons = sb + OFF_B + wc * 4096 + (lane << 4);
    const uint32_t b2cons = sb + OFF_B2 + wc * 256 + lane * 8;  // lora slot ksl == wc

    float acc[4][4][4];
    float accL[4][4];
    #pragma unroll
    for (int a = 0; a < 4; ++a) {
        #pragma unroll
        for (int b = 0; b < 4; ++b)
            acc[a][b][0] = acc[a][b][1] = acc[a][b][2] = acc[a][b][3] = 0.f;
        accL[a][0] = accL[a][1] = accL[a][2] = accL[a][3] = 0.f;
    }

    if (tid == 0) {
        #pragma unroll
        for (int st = 0; st < STAGES; ++st) MBAR_INIT(sb + OFF_BAR + 8 * st, 1);
        MBAR_EXPECT(sb + OFF_BAR + 0, TX_BYTES);
        MBAR_EXPECT(sb + OFF_BAR + 8, TX_BYTES);
    }
    __syncthreads();

    auto issue = [&](int slice, int st) {
        if (lane == 0) {
            uint32_t mb = sb + OFF_BAR + 8 * st;
            const float* xs = x + (size_t)(m0 + wid * 16) * K_TOTAL + slice * 32;
            uint32_t ad = sb + OFF_A + st * A_STG + (wid * 16) * 144;
            #pragma unroll
            for (int r = 0; r < 16; ++r)
                bulk_cp(ad + r * 144, xs + (size_t)r * K_TOTAL, 128, mb);
            if (wid == 6) bulk_cp(sb + OFF_B + st * B_STG, wsrc + (size_t)slice * 4096, 16384, mb);
            if (wid == 5) bulk_cp(sb + OFF_B2 + st * B2_STG, wdsrc + slice * 256, 1024, mb);
        }
    };
    issue(0, 0);
    issue(1, 1);

    auto compute_slice = [&](int st) {
        const uint32_t ab = abase0 + st * A_STG;
        const uint32_t bb = bcons + st * B_STG;
        #pragma unroll
        for (int ksl = 0; ksl < 4; ++ksl) {
            uint32_t a[4][4];
            #pragma unroll
            for (int mf = 0; mf < 4; ++mf)
                asm volatile("ldmatrix.sync.aligned.m8n8.x4.shared.b16 {%0,%1,%2,%3}, [%4];"
                             : "=r"(a[mf][0]), "=r"(a[mf][1]), "=r"(a[mf][2]), "=r"(a[mf][3])
                             : "r"(ab + mf * 16 * 144 + ksl * 32));
            #pragma unroll
            for (int nfp = 0; nfp < 2; ++nfp) {
                uint32_t b[4];
                asm volatile("ld.shared.v4.b32 {%0,%1,%2,%3}, [%4];"
                             : "=r"(b[0]), "=r"(b[1]), "=r"(b[2]), "=r"(b[3])
                             : "r"(bb + (((nfp * 4 + ksl) * 32) << 4)));
                #pragma unroll
                for (int mf = 0; mf < 4; ++mf) {
                    mma8(acc[mf][2 * nfp], a[mf], b[0], b[1]);
                    mma8(acc[mf][2 * nfp + 1], a[mf], b[2], b[3]);
                }
            }
            if (wc == ksl) {   // one lora warp per SMSP per row-half
                uint32_t bl[2];
                asm volatile("ld.shared.v2.b32 {%0,%1}, [%2];"
                             : "=r"(bl[0]), "=r"(bl[1]) : "r"(b2cons + st * B2_STG));
                #pragma unroll
                for (int mf = 0; mf < 4; ++mf) mma8(accL[mf], a[mf], bl[0], bl[1]);
            }
        }
    };

    // ---- main loop: 2 slices per barrier block, 3 rotating stages
    #pragma unroll 1
    for (int s = 0; s < SLICES; s += 2) {
        const int st0 = s % 3, ph0 = (s / 3) & 1;
        const int st1 = (s + 1) % 3, ph1 = ((s + 1) / 3) & 1;
        MBAR_WAIT(sb + OFF_BAR + 8 * st0, ph0);
        compute_slice(st0);
        MBAR_WAIT(sb + OFF_BAR + 8 * st1, ph1);
        compute_slice(st1);
        if (tid == 0) {
            if (s + 2 < SLICES) MBAR_EXPECT(sb + OFF_BAR + 8 * ((s + 2) % 3), TX_BYTES);
            if (s + 3 < SLICES) MBAR_EXPECT(sb + OFF_BAR + 8 * ((s + 3) % 3), TX_BYTES);
        }
        __syncthreads();
        if (s + 2 < SLICES) issue(s + 2, (s + 2) % 3);
        if (s + 3 < SLICES) issue(s + 3, (s + 3) % 3);
    }

    // ---- epilogue: A-stage space is dead; alias WU + DN partials there
    __syncthreads();
    if (tid < 128) ((float4*)(smem + OFF_WU))[tid] = wuv;
    float* dns = (float*)(smem + OFF_DN);
    if (tig < 2) {
        float* db = dns + wc * 512;
        #pragma unroll
        for (int mf = 0; mf < 4; ++mf) {
            int mlo = wr * 64 + mf * 16 + gid, mhi = mlo + 8;
            db[mlo * 4 + 2 * tig] = accL[mf][0] * coeff;
            db[mlo * 4 + 2 * tig + 1] = accL[mf][1] * coeff;
            db[mhi * 4 + 2 * tig] = accL[mf][2] * coeff;
            db[mhi * 4 + 2 * tig + 1] = accL[mf][3] * coeff;
        }
    }
    __syncthreads();

    const float4* wus = (const float4*)(smem + OFF_WU);
    const float4* d0 = (const float4*)(dns);
    const float4* d1 = (const float4*)(dns + 512);
    const float4* d2 = (const float4*)(dns + 1024);
    const float4* d3 = (const float4*)(dns + 1536);
    #pragma unroll
    for (int mf = 0; mf < 4; ++mf) {
        int mlo = wr * 64 + mf * 16 + gid, mhi = mlo + 8;
        float4 a0 = d0[mlo], a1 = d1[mlo], a2 = d2[mlo], a3 = d3[mlo];
        float4 dlo = make_float4(a0.x + a1.x + a2.x + a3.x, a0.y + a1.y + a2.y + a3.y,
                                 a0.z + a1.z + a2.z + a3.z, a0.w + a1.w + a2.w + a3.w);
        float4 b0 = d0[mhi], b1 = d1[mhi], b2 = d2[mhi], b3 = d3[mhi];
        float4 dhi = make_float4(b0.x + b1.x + b2.x + b3.x, b0.y + b1.y + b2.y + b3.y,
                                 b0.z + b1.z + b2.z + b3.z, b0.w + b1.w + b2.w + b3.w);
        float* olo = out + (size_t)(m0 + mlo) * N_TOTAL + nb;
        float* ohi = out + (size_t)(m0 + mhi) * N_TOTAL + nb;
        #pragma unroll
        for (int nf = 0; nf < 4; ++nf) {
            int n = wc * 32 + nf * 8 + 2 * tig;
            float4 w0 = wus[n], w1 = wus[n + 1];
            float2 vlo, vhi;
            vlo.x = acc[mf][nf][0] + dlo.x * w0.x + dlo.y * w0.y + dlo.z * w0.z + dlo.w * w0.w;
            vlo.y = acc[mf][nf][1] + dlo.x * w1.x + dlo.y * w1.y + dlo.z * w1.z + dlo.w * w1.w;
            vhi.x = acc[mf][nf][2] + dhi.x * w0.x + dhi.y * w0.y + dhi.z * w0.z + dhi.w * w0.w;
            vhi.y = acc[mf][nf][3] + dhi.x * w1.x + dhi.y * w1.y + dhi.z * w1.z + dhi.w * w1.w;
            *(float2*)(olo + n) = vlo;
            *(float2*)(ohi + n) = vhi;
        }
    }
}

extern "C" void kernel_launch(void* const* d_in, const int* in_sizes, int n_in,
                              void* d_out, int out_size) {
    const float* x = (const float*)d_in[0];
    const int* lid = (const int*)d_in[1];
    const float* W = (const float*)d_in[2];
    const float* Wd = (const float*)d_in[3];
    const float* Wu = (const float*)d_in[4];
    float* out = (float*)d_out;

    cudaFuncSetAttribute(lora_gemm, cudaFuncAttributeMaxDynamicSharedMemorySize, SMEM_BYTES);
    int total = N_TOTAL * K_TOTAL + 50 * K_TOTAL * 8;
    prep_kernel<<<(total + 255) / 256, 256>>>(W, Wd);
    lora_gemm<<<GRID, THREADS, SMEM_BYTES>>>(x, lid, Wu, out);
}

// round 15
// speedup vs baseline: 1.1290x; 1.1290x over previous
#include <cuda_runtime.h>
#include <cuda.h>
#include <cstdint>

static constexpr int K_TOTAL = 1280, N_TOTAL = 1280;
static constexpr int BM = 128, BN = 256;
static constexpr int SLICES = 40;
static constexpr int NTILES = 5, MTILES = 512;
static constexpr int GRID = NTILES * MTILES;   // 2560
static constexpr int THREADS = 512;
static constexpr int STAGES = 4;

static constexpr int A_STG = 16384;   // 128 rows * 128B, SW128 (TMA tile)
static constexpr int B_STG = 32768;
static constexpr int B2_STG = 1024;
static constexpr int OFF_A = 0;                  // 4*16384 = 65536
static constexpr int OFF_B = 65536;              // 4*32768 = 131072 -> 196608
static constexpr int OFF_B2 = 196608;            // 4096
static constexpr int OFF_WU = 200704;            // 4096
static constexpr int OFF_DN = 204800;            // 8192 (4 partial buffers)
static constexpr int OFF_BAR = 212992;
static constexpr int SMEM_BYTES = 213504;
static constexpr unsigned TX_BYTES = 16384u + 32768u + 1024u;

// W fragments, per 32-k slice block of 8192 floats:
// (((pair*4+ks)*32 + gid*4 + tig)*4 + nfo*2 + kh), pair = n16-group 0..15
__device__ __align__(16) float g_Wfrag[NTILES * SLICES * 8192];
// Wd fragments: [lora][slice32][(ks*32+lane)*2 + kh]
__device__ __align__(16) float g_Wdfrag[50 * SLICES * 256];

__device__ __forceinline__ uint32_t smem_u32(const void* p) {
    uint32_t a;
    asm("{ .reg .u64 t; cvta.to.shared.u64 t, %1; cvt.u32.u64 %0, t; }" : "=r"(a) : "l"(p));
    return a;
}
__device__ __forceinline__ uint32_t rna(float f) {
    uint32_t b;
    asm("cvt.rna.tf32.f32 %0, %1;" : "=r"(b) : "f"(f));
    return b;
}
__device__ __forceinline__ void mma8(float* c, const uint32_t* a, uint32_t b0, uint32_t b1) {
    asm volatile(
        "mma.sync.aligned.m16n8k8.row.col.f32.tf32.tf32.f32 "
        "{%0,%1,%2,%3}, {%4,%5,%6,%7}, {%8,%9}, {%0,%1,%2,%3};"
        : "+f"(c[0]), "+f"(c[1]), "+f"(c[2]), "+f"(c[3])
        : "r"(a[0]), "r"(a[1]), "r"(a[2]), "r"(a[3]), "r"(b0), "r"(b1));
}
__device__ __forceinline__ void bulk_cp(uint32_t dst, const void* src, uint32_t bytes, uint32_t mb) {
    asm volatile(
        "cp.async.bulk.shared::cta.global.mbarrier::complete_tx::bytes [%0], [%1], %2, [%3];"
        :: "r"(dst), "l"(src), "r"(bytes), "r"(mb) : "memory");
}
#define MBAR_INIT(a, c) \
    asm volatile("mbarrier.init.shared.b64 [%0], %1;" :: "r"((uint32_t)(a)), "r"((uint32_t)(c)) : "memory")
#define MBAR_EXPECT(a, tx) \
    asm volatile("mbarrier.arrive.expect_tx.shared.b64 _, [%0], %1;" :: "r"((uint32_t)(a)), "r"((uint32_t)(tx)) : "memory")
#define MBAR_WAIT(a, ph) do { \
    uint32_t _m = (uint32_t)(a), _p = (uint32_t)(ph), _d; \
    asm volatile("{ .reg .pred p; mbarrier.try_wait.parity.acquire.cta.shared::cta.b64 p, [%1], %2; selp.b32 %0, 1, 0, p; }" \
        : "=r"(_d) : "r"(_m), "r"(_p) : "memory"); \
    if (!_d) { \
        asm volatile("{ .reg .pred P1;\nWL_%=: mbarrier.try_wait.parity.acquire.cta.shared::cta.b64 P1, [%0], %1, 0x989680;\n@P1 bra.uni WD_%=;\nbra.uni WL_%=;\nWD_%=: }" \
            :: "r"(_m), "r"(_p) : "memory"); \
    } \
} while (0)

// ---------------- prepass (unchanged fragment convention)
__global__ void prep_kernel(const float* __restrict__ W, const float* __restrict__ Wd) {
    int i = blockIdx.x * blockDim.x + threadIdx.x;
    const int NW = N_TOTAL * K_TOTAL;
    if (i < NW) {
        int n = i / K_TOTAL, k = i % K_TOTAL;
        int ntile = n >> 8, nn = n & 255;
        int pair = nn >> 4, nfo = (nn >> 3) & 1, gid = nn & 7;
        int slice = k >> 5, ks = (k >> 3) & 3, kh = (k >> 2) & 1, tig = k & 3;
        int off = (ntile * SLICES + slice) * 8192 +
                  (((pair * 4 + ks) * 32 + gid * 4 + tig) * 4 + nfo * 2 + kh);
        g_Wfrag[off] = __uint_as_float(rna(W[i]));
    } else if (i < NW + 50 * K_TOTAL * 8) {
        int j = i - NW;
        int gid = j & 7, t = j >> 3, k = t % K_TOTAL, l = t / K_TOTAL;
        float v = 0.f;
        if (gid < 4) v = __uint_as_float(rna(Wd[(l * 4 + gid) * K_TOTAL + k]));
        int slice = k >> 5, ks = (k >> 3) & 3, kh = (k >> 2) & 1, tig = k & 3;
        g_Wdfrag[(l * SLICES + slice) * 256 + (ks * 32 + gid * 4 + tig) * 2 + kh] = v;
    }
}

// ---------------- main fused kernel: TMA tensor A feed, 512 threads
__global__ void __launch_bounds__(THREADS, 1)
lora_gemm(const __grid_constant__ CUtensorMap tmap,
          const int* __restrict__ lora_id,
          const float* __restrict__ Wu, float* __restrict__ out) {
    extern __shared__ char smem[];
    const uint32_t sb = smem_u32(smem);
    const int tid = threadIdx.x, lane = tid & 31, wid = tid >> 5;
    const int bid = blockIdx.x;
    const int ntile = bid % NTILES, mtile = bid / NTILES;
    const int m0 = mtile * BM, nb = ntile * BN;

    const int id = lora_id[m0 >> 12];
    const int idx = (id >= 0) ? ((id >> 2) > 49 ? 49 : (id >> 2)) : 0;
    const float coeff = (id >= 0) ? 1.f : 0.f;

    if (tid < 256) {
        const float4* wusrc = (const float4*)Wu + (size_t)idx * N_TOTAL;
        ((float4*)(smem + OFF_WU))[tid] = wusrc[nb + tid];
    }

    const int gid = lane >> 2, tig = lane & 3;
    const int wr = wid >> 3, wc = wid & 7;   // 2 x 8 warp grid, warp tile 64x32

    const float* wsrc = g_Wfrag + (size_t)ntile * SLICES * 8192;
    const float* wdsrc = g_Wdfrag + (size_t)idx * SLICES * 256;

    // SW128 ldmatrix addressing: row = wr*64 + (lane&15) (+16*mf), chunk = ksl*2 + (lane>>4)
    // smem addr = row*128 + ((chunk ^ (row&7))<<4); row&7 == lane&7 for all mf.
    const uint32_t abase0 = sb + OFF_A + (wr * 64 + (lane & 15)) * 128;
    const uint32_t hi16 = (lane >> 4) << 4;
    const uint32_t sxor = (lane & 7) << 4;
    const uint32_t bcons = sb + OFF_B + wc * 4096 + (lane << 4);
    const uint32_t b2cons = sb + OFF_B2 + (wc & 3) * 256 + lane * 8;

    float acc[4][4][4];
    float accL[4][4];
    #pragma unroll
    for (int a = 0; a < 4; ++a) {
        #pragma unroll
        for (int b = 0; b < 4; ++b)
            acc[a][b][0] = acc[a][b][1] = acc[a][b][2] = acc[a][b][3] = 0.f;
        accL[a][0] = accL[a][1] = accL[a][2] = accL[a][3] = 0.f;
    }

    if (tid == 0) {
        #pragma unroll
        for (int st = 0; st < STAGES; ++st) MBAR_INIT(sb + OFF_BAR + 8 * st, 1);
    }
    __syncthreads();

    auto issue = [&](int slice, int st) {
        if (tid == 0) {
            uint32_t mb = sb + OFF_BAR + 8 * st;
            MBAR_EXPECT(mb, TX_BYTES);
            asm volatile(
                "cp.async.bulk.tensor.2d.shared::cta.global.tile.mbarrier::complete_tx::bytes "
                "[%0], [%1, {%2, %3}], [%4];"
                :: "r"(sb + OFF_A + st * A_STG), "l"(&tmap),
                   "r"(slice * 32), "r"(m0), "r"(mb) : "memory");
            bulk_cp(sb + OFF_B + st * B_STG, wsrc + (size_t)slice * 8192, 32768, mb);
            bulk_cp(sb + OFF_B2 + st * B2_STG, wdsrc + slice * 256, 1024, mb);
        }
    };
    issue(0, 0);
    issue(1, 1);
    issue(2, 2);

    // ---- main loop over 32-k slices, 4-stage pipeline
    #pragma unroll 1
    for (int s = 0; s < SLICES; ++s) {
        const int st = s & 3;
        MBAR_WAIT(sb + OFF_BAR + 8 * st, (s >> 2) & 1);

        const uint32_t ab = abase0 + st * A_STG;
        const uint32_t bb = bcons + st * B_STG;
        #pragma unroll
        for (int ksl = 0; ksl < 4; ++ksl) {
            const uint32_t aoff = ((uint32_t)(ksl << 5) | hi16) ^ sxor;
            uint32_t a[4][4];
            #pragma unroll
            for (int mf = 0; mf < 4; ++mf)
                asm volatile("ldmatrix.sync.aligned.m8n8.x4.shared.b16 {%0,%1,%2,%3}, [%4];"
                             : "=r"(a[mf][0]), "=r"(a[mf][1]), "=r"(a[mf][2]), "=r"(a[mf][3])
                             : "r"(ab + mf * 2048 + aoff));
            #pragma unroll
            for (int nfp = 0; nfp < 2; ++nfp) {
                uint32_t b[4];
                asm volatile("ld.shared.v4.b32 {%0,%1,%2,%3}, [%4];"
                             : "=r"(b[0]), "=r"(b[1]), "=r"(b[2]), "=r"(b[3])
                             : "r"(bb + (((nfp * 4 + ksl) * 32) << 4)));
                #pragma unroll
                for (int mf = 0; mf < 4; ++mf) {
                    mma8(acc[mf][2 * nfp], a[mf], b[0], b[1]);
                    mma8(acc[mf][2 * nfp + 1], a[mf], b[2], b[3]);
                }
            }
            if ((wc & 3) == ksl && wc < 4) {   // one lora warp per SMSP
                uint32_t bl[2];
                asm volatile("ld.shared.v2.b32 {%0,%1}, [%2];"
                             : "=r"(bl[0]), "=r"(bl[1]) : "r"(b2cons + st * B2_STG));
                #pragma unroll
                for (int mf = 0; mf < 4; ++mf) mma8(accL[mf], a[mf], bl[0], bl[1]);
            }
        }
        __syncthreads();
        if (s + 3 < SLICES) issue(s + 3, (s + 3) & 3);
    }

    // ---- epilogue: 4 partial DN buffers, fused add + store
    float* dns = (float*)(smem + OFF_DN);
    if (wc < 4 && tig < 2) {
        float* db = dns + wc * 512;
        #pragma unroll
        for (int mf = 0; mf < 4; ++mf) {
            int mlo = wr * 64 + mf * 16 + gid, mhi = mlo + 8;
            db[mlo * 4 + 2 * tig] = accL[mf][0] * coeff;
            db[mlo * 4 + 2 * tig + 1] = accL[mf][1] * coeff;
            db[mhi * 4 + 2 * tig] = accL[mf][2] * coeff;
            db[mhi * 4 + 2 * tig + 1] = accL[mf][3] * coeff;
        }
    }
    __syncthreads();

    const float4* wus = (const float4*)(smem + OFF_WU);
    const float4* d0 = (const float4*)(dns);
    const float4* d1 = (const float4*)(dns + 512);
    const float4* d2 = (const float4*)(dns + 1024);
    const float4* d3 = (const float4*)(dns + 1536);
    #pragma unroll
    for (int mf = 0; mf < 4; ++mf) {
        int mlo = wr * 64 + mf * 16 + gid, mhi = mlo + 8;
        float4 a0 = d0[mlo], a1 = d1[mlo], a2 = d2[mlo], a3 = d3[mlo];
        float4 dlo = make_float4(a0.x + a1.x + a2.x + a3.x, a0.y + a1.y + a2.y + a3.y,
                                 a0.z + a1.z + a2.z + a3.z, a0.w + a1.w + a2.w + a3.w);
        float4 b0 = d0[mhi], b1 = d1[mhi], b2 = d2[mhi], b3 = d3[mhi];
        float4 dhi = make_float4(b0.x + b1.x + b2.x + b3.x, b0.y + b1.y + b2.y + b3.y,
                                 b0.z + b1.z + b2.z + b3.z, b0.w + b1.w + b2.w + b3.w);
        float* olo = out + (size_t)(m0 + mlo) * N_TOTAL + nb;
        float* ohi = out + (size_t)(m0 + mhi) * N_TOTAL + nb;
        #pragma unroll
        for (int nf = 0; nf < 4; ++nf) {
            int n = wc * 32 + nf * 8 + 2 * tig;
            float4 w0 = wus[n], w1 = wus[n + 1];
            float2 vlo, vhi;
            vlo.x = acc[mf][nf][0] + dlo.x * w0.x + dlo.y * w0.y + dlo.z * w0.z + dlo.w * w0.w;
            vlo.y = acc[mf][nf][1] + dlo.x * w1.x + dlo.y * w1.y + dlo.z * w1.z + dlo.w * w1.w;
            vhi.x = acc[mf][nf][2] + dhi.x * w0.x + dhi.y * w0.y + dhi.z * w0.z + dhi.w * w0.w;
            vhi.y = acc[mf][nf][3] + dhi.x * w1.x + dhi.y * w1.y + dhi.z * w1.z + dhi.w * w1.w;
            *(float2*)(olo + n) = vlo;
            *(float2*)(ohi + n) = vhi;
        }
    }
}

typedef CUresult (*EncodeTiledFn)(
    CUtensorMap*, CUtensorMapDataType, cuuint32_t, void*,
    const cuuint64_t*, const cuuint64_t*, const cuuint32_t*, const cuuint32_t*,
    CUtensorMapInterleave, CUtensorMapSwizzle, CUtensorMapL2promotion,
    CUtensorMapFloatOOBfill);

extern "C" void kernel_launch(void* const* d_in, const int* in_sizes, int n_in,
                              void* d_out, int out_size) {
    const float* x = (const float*)d_in[0];
    const int* lid = (const int*)d_in[1];
    const float* W = (const float*)d_in[2];
    const float* Wd = (const float*)d_in[3];
    const float* Wu = (const float*)d_in[4];
    float* out = (float*)d_out;

    // tensormap for x: (K, M) fp32, box (32, 128), SW128
    void* fp = nullptr;
    cudaDriverEntryPointQueryResult qr;
    cudaGetDriverEntryPoint("cuTensorMapEncodeTiled", &fp, cudaEnableDefault, &qr);
    EncodeTiledFn enc = (EncodeTiledFn)fp;
    CUtensorMap tmap;
    cuuint64_t dims[2] = {(cuuint64_t)K_TOTAL, 65536ull};
    cuuint64_t strides[1] = {(cuuint64_t)K_TOTAL * 4};
    cuuint32_t box[2] = {32, 128};
    cuuint32_t es[2] = {1, 1};
    enc(&tmap, CU_TENSOR_MAP_DATA_TYPE_FLOAT32, 2, (void*)x,
        dims, strides, box, es,
        CU_TENSOR_MAP_INTERLEAVE_NONE, CU_TENSOR_MAP_SWIZZLE_128B,
        CU_TENSOR_MAP_L2_PROMOTION_L2_128B, CU_TENSOR_MAP_FLOAT_OOB_FILL_NONE);

    cudaFuncSetAttribute(lora_gemm, cudaFuncAttributeMaxDynamicSharedMemorySize, SMEM_BYTES);
    int total = N_TOTAL * K_TOTAL + 50 * K_TOTAL * 8;
    prep_kernel<<<(total + 255) / 256, 256>>>(W, Wd);
    lora_gemm<<<GRID, THREADS, SMEM_BYTES>>>(tmap, lid, Wu, out);
}

// round 16
// speedup vs baseline: 1.1509x; 1.0194x over previous
#include <cuda_runtime.h>
#include <cuda.h>
#include <cstdint>

static constexpr int K_TOTAL = 1280, N_TOTAL = 1280;
static constexpr int BM = 128, BN = 256;
static constexpr int SLICES = 40;
static constexpr int NTILES = 5, MTILES = 512;
static constexpr int GRID = NTILES * MTILES;   // 2560
static constexpr int THREADS = 512;
static constexpr int STAGES = 4;

static constexpr int A_STG = 16384;   // 128 rows * 128B, SW128 (TMA tile)
static constexpr int B_STG = 32768;
static constexpr int B2_STG = 1024;
static constexpr int OFF_A = 0;
static constexpr int OFF_B = 65536;
static constexpr int OFF_B2 = 196608;
static constexpr int OFF_WU = 200704;
static constexpr int OFF_DN = 204800;
static constexpr int OFF_BAR = 212992;
static constexpr int SMEM_BYTES = 213504;
static constexpr unsigned TX_BYTES = 16384u + 32768u + 1024u;

// W fragments, per 32-k slice block of 8192 floats:
// (((pair*4+ks)*32 + gid*4 + tig)*4 + nfo*2 + kh), pair = n16-group 0..15
__device__ __align__(16) float g_Wfrag[NTILES * SLICES * 8192];
// Wd fragments: [lora][slice32][(ks*32+lane)*2 + kh]
__device__ __align__(16) float g_Wdfrag[50 * SLICES * 256];

__device__ __forceinline__ uint32_t smem_u32(const void* p) {
    uint32_t a;
    asm("{ .reg .u64 t; cvta.to.shared.u64 t, %1; cvt.u32.u64 %0, t; }" : "=r"(a) : "l"(p));
    return a;
}
__device__ __forceinline__ uint32_t rna(float f) {
    uint32_t b;
    asm("cvt.rna.tf32.f32 %0, %1;" : "=r"(b) : "f"(f));
    return b;
}
__device__ __forceinline__ void mma8(float* c, const uint32_t* a, uint32_t b0, uint32_t b1) {
    asm volatile(
        "mma.sync.aligned.m16n8k8.row.col.f32.tf32.tf32.f32 "
        "{%0,%1,%2,%3}, {%4,%5,%6,%7}, {%8,%9}, {%0,%1,%2,%3};"
        : "+f"(c[0]), "+f"(c[1]), "+f"(c[2]), "+f"(c[3])
        : "r"(a[0]), "r"(a[1]), "r"(a[2]), "r"(a[3]), "r"(b0), "r"(b1));
}
__device__ __forceinline__ void bulk_cp(uint32_t dst, const void* src, uint32_t bytes, uint32_t mb) {
    asm volatile(
        "cp.async.bulk.shared::cta.global.mbarrier::complete_tx::bytes [%0], [%1], %2, [%3];"
        :: "r"(dst), "l"(src), "r"(bytes), "r"(mb) : "memory");
}
#define MBAR_INIT(a, c) \
    asm volatile("mbarrier.init.shared.b64 [%0], %1;" :: "r"((uint32_t)(a)), "r"((uint32_t)(c)) : "memory")
#define MBAR_EXPECT(a, tx) \
    asm volatile("mbarrier.arrive.expect_tx.shared.b64 _, [%0], %1;" :: "r"((uint32_t)(a)), "r"((uint32_t)(tx)) : "memory")
#define MBAR_WAIT(a, ph) do { \
    uint32_t _m = (uint32_t)(a), _p = (uint32_t)(ph), _d; \
    asm volatile("{ .reg .pred p; mbarrier.try_wait.parity.acquire.cta.shared::cta.b64 p, [%1], %2; selp.b32 %0, 1, 0, p; }" \
        : "=r"(_d) : "r"(_m), "r"(_p) : "memory"); \
    if (!_d) { \
        asm volatile("{ .reg .pred P1;\nWL_%=: mbarrier.try_wait.parity.acquire.cta.shared::cta.b64 P1, [%0], %1, 0x989680;\n@P1 bra.uni WD_%=;\nbra.uni WL_%=;\nWD_%=: }" \
            :: "r"(_m), "r"(_p) : "memory"); \
    } \
} while (0)

// ---------------- prepass (unchanged fragment convention)
__global__ void prep_kernel(const float* __restrict__ W, const float* __restrict__ Wd) {
    int i = blockIdx.x * blockDim.x + threadIdx.x;
    const int NW = N_TOTAL * K_TOTAL;
    if (i < NW) {
        int n = i / K_TOTAL, k = i % K_TOTAL;
        int ntile = n >> 8, nn = n & 255;
        int pair = nn >> 4, nfo = (nn >> 3) & 1, gid = nn & 7;
        int slice = k >> 5, ks = (k >> 3) & 3, kh = (k >> 2) & 1, tig = k & 3;
        int off = (ntile * SLICES + slice) * 8192 +
                  (((pair * 4 + ks) * 32 + gid * 4 + tig) * 4 + nfo * 2 + kh);
        g_Wfrag[off] = __uint_as_float(rna(W[i]));
    } else if (i < NW + 50 * K_TOTAL * 8) {
        int j = i - NW;
        int gid = j & 7, t = j >> 3, k = t % K_TOTAL, l = t / K_TOTAL;
        float v = 0.f;
        if (gid < 4) v = __uint_as_float(rna(Wd[(l * 4 + gid) * K_TOTAL + k]));
        int slice = k >> 5, ks = (k >> 3) & 3, kh = (k >> 2) & 1, tig = k & 3;
        g_Wdfrag[(l * SLICES + slice) * 256 + (ks * 32 + gid * 4 + tig) * 2 + kh] = v;
    }
}

// ---------------- main fused kernel: TMA A feed, 2 slices per barrier
__global__ void __launch_bounds__(THREADS, 1)
lora_gemm(const __grid_constant__ CUtensorMap tmap,
          const int* __restrict__ lora_id,
          const float* __restrict__ Wu, float* __restrict__ out) {
    extern __shared__ char smem[];
    const uint32_t sb = smem_u32(smem);
    const int tid = threadIdx.x, lane = tid & 31, wid = tid >> 5;
    const int bid = blockIdx.x;
    const int ntile = bid % NTILES, mtile = bid / NTILES;
    const int m0 = mtile * BM, nb = ntile * BN;

    const int id = lora_id[m0 >> 12];
    const int idx = (id >= 0) ? ((id >> 2) > 49 ? 49 : (id >> 2)) : 0;
    const float coeff = (id >= 0) ? 1.f : 0.f;

    if (tid < 256) {
        const float4* wusrc = (const float4*)Wu + (size_t)idx * N_TOTAL;
        ((float4*)(smem + OFF_WU))[tid] = wusrc[nb + tid];
    }

    const int gid = lane >> 2, tig = lane & 3;
    const int wr = wid >> 3, wc = wid & 7;   // 2 x 8 warp grid, warp tile 64x32

    const float* wsrc = g_Wfrag + (size_t)ntile * SLICES * 8192;
    const float* wdsrc = g_Wdfrag + (size_t)idx * SLICES * 256;

    const uint32_t abase0 = sb + OFF_A + (wr * 64 + (lane & 15)) * 128;
    const uint32_t hi16 = (lane >> 4) << 4;
    const uint32_t sxor = (lane & 7) << 4;
    const uint32_t bcons = sb + OFF_B + wc * 4096 + (lane << 4);
    const uint32_t b2cons = sb + OFF_B2 + (wc & 3) * 256 + lane * 8;

    float acc[4][4][4];
    float accL[4][4];
    #pragma unroll
    for (int a = 0; a < 4; ++a) {
        #pragma unroll
        for (int b = 0; b < 4; ++b)
            acc[a][b][0] = acc[a][b][1] = acc[a][b][2] = acc[a][b][3] = 0.f;
        accL[a][0] = accL[a][1] = accL[a][2] = accL[a][3] = 0.f;
    }

    if (tid == 0) {
        #pragma unroll
        for (int st = 0; st < STAGES; ++st) MBAR_INIT(sb + OFF_BAR + 8 * st, 1);
    }
    __syncthreads();

    auto issue = [&](int slice, int st) {
        if (tid == 0) {
            uint32_t mb = sb + OFF_BAR + 8 * st;
            MBAR_EXPECT(mb, TX_BYTES);
            asm volatile(
                "cp.async.bulk.tensor.2d.shared::cta.global.tile.mbarrier::complete_tx::bytes "
                "[%0], [%1, {%2, %3}], [%4];"
                :: "r"(sb + OFF_A + st * A_STG), "l"(&tmap),
                   "r"(slice * 32), "r"(m0), "r"(mb) : "memory");
            bulk_cp(sb + OFF_B + st * B_STG, wsrc + (size_t)slice * 8192, 32768, mb);
            bulk_cp(sb + OFF_B2 + st * B2_STG, wdsrc + slice * 256, 1024, mb);
        }
    };
    issue(0, 0);
    issue(1, 1);
    issue(2, 2);
    issue(3, 3);

    auto compute_slice = [&](int st) {
        const uint32_t ab = abase0 + st * A_STG;
        const uint32_t bb = bcons + st * B_STG;
        #pragma unroll
        for (int ksl = 0; ksl < 4; ++ksl) {
            const uint32_t aoff = ((uint32_t)(ksl << 5) | hi16) ^ sxor;
            uint32_t a[4][4];
            #pragma unroll
            for (int mf = 0; mf < 4; ++mf)
                asm volatile("ldmatrix.sync.aligned.m8n8.x4.shared.b16 {%0,%1,%2,%3}, [%4];"
                             : "=r"(a[mf][0]), "=r"(a[mf][1]), "=r"(a[mf][2]), "=r"(a[mf][3])
                             : "r"(ab + mf * 2048 + aoff));
            #pragma unroll
            for (int nfp = 0; nfp < 2; ++nfp) {
                uint32_t b[4];
                asm volatile("ld.shared.v4.b32 {%0,%1,%2,%3}, [%4];"
                             : "=r"(b[0]), "=r"(b[1]), "=r"(b[2]), "=r"(b[3])
                             : "r"(bb + (((nfp * 4 + ksl) * 32) << 4)));
                #pragma unroll
                for (int mf = 0; mf < 4; ++mf) {
                    mma8(acc[mf][2 * nfp], a[mf], b[0], b[1]);
                    mma8(acc[mf][2 * nfp + 1], a[mf], b[2], b[3]);
                }
            }
            if ((wc & 3) == ksl && wc < 4) {   // one lora warp per SMSP
                uint32_t bl[2];
                asm volatile("ld.shared.v2.b32 {%0,%1}, [%2];"
                             : "=r"(bl[0]), "=r"(bl[1]) : "r"(b2cons + st * B2_STG));
                #pragma unroll
                for (int mf = 0; mf < 4; ++mf) mma8(accL[mf], a[mf], bl[0], bl[1]);
            }
        }
    };

    // ---- main loop: 2 slices per barrier block, full 4-deep prefetch
    #pragma unroll 1
    for (int s = 0; s < SLICES; s += 2) {
        MBAR_WAIT(sb + OFF_BAR + 8 * (s & 3), (s >> 2) & 1);
        compute_slice(s & 3);
        MBAR_WAIT(sb + OFF_BAR + 8 * ((s + 1) & 3), ((s + 1) >> 2) & 1);
        compute_slice((s + 1) & 3);
        __syncthreads();
        if (s + 4 < SLICES) issue(s + 4, (s + 4) & 3);
        if (s + 5 < SLICES) issue(s + 5, (s + 5) & 3);
    }

    // ---- epilogue: 4 partial DN buffers, fused add + store
    float* dns = (float*)(smem + OFF_DN);
    if (wc < 4 && tig < 2) {
        float* db = dns + wc * 512;
        #pragma unroll
        for (int mf = 0; mf < 4; ++mf) {
            int mlo = wr * 64 + mf * 16 + gid, mhi = mlo + 8;
            db[mlo * 4 + 2 * tig] = accL[mf][0] * coeff;
            db[mlo * 4 + 2 * tig + 1] = accL[mf][1] * coeff;
            db[mhi * 4 + 2 * tig] = accL[mf][2] * coeff;
            db[mhi * 4 + 2 * tig + 1] = accL[mf][3] * coeff;
        }
    }
    __syncthreads();

    const float4* wus = (const float4*)(smem + OFF_WU);
    const float4* d0 = (const float4*)(dns);
    const float4* d1 = (const float4*)(dns + 512);
    const float4* d2 = (const float4*)(dns + 1024);
    const float4* d3 = (const float4*)(dns + 1536);
    #pragma unroll
    for (int mf = 0; mf < 4; ++mf) {
        int mlo = wr * 64 + mf * 16 + gid, mhi = mlo + 8;
        float4 a0 = d0[mlo], a1 = d1[mlo], a2 = d2[mlo], a3 = d3[mlo];
        float4 dlo = make_float4(a0.x + a1.x + a2.x + a3.x, a0.y + a1.y + a2.y + a3.y,
                                 a0.z + a1.z + a2.z + a3.z, a0.w + a1.w + a2.w + a3.w);
        float4 b0 = d0[mhi], b1 = d1[mhi], b2 = d2[mhi], b3 = d3[mhi];
        float4 dhi = make_float4(b0.x + b1.x + b2.x + b3.x, b0.y + b1.y + b2.y + b3.y,
                                 b0.z + b1.z + b2.z + b3.z, b0.w + b1.w + b2.w + b3.w);
        float* olo = out + (size_t)(m0 + mlo) * N_TOTAL + nb;
        float* ohi = out + (size_t)(m0 + mhi) * N_TOTAL + nb;
        #pragma unroll
        for (int nf = 0; nf < 4; ++nf) {
            int n = wc * 32 + nf * 8 + 2 * tig;
            float4 w0 = wus[n], w1 = wus[n + 1];
            float2 vlo, vhi;
            vlo.x = acc[mf][nf][0] + dlo.x * w0.x + dlo.y * w0.y + dlo.z * w0.z + dlo.w * w0.w;
            vlo.y = acc[mf][nf][1] + dlo.x * w1.x + dlo.y * w1.y + dlo.z * w1.z + dlo.w * w1.w;
            vhi.x = acc[mf][nf][2] + dhi.x * w0.x + dhi.y * w0.y + dhi.z * w0.z + dhi.w * w0.w;
            vhi.y = acc[mf][nf][3] + dhi.x * w1.x + dhi.y * w1.y + dhi.z * w1.z + dhi.w * w1.w;
            *(float2*)(olo + n) = vlo;
            *(float2*)(ohi + n) = vhi;
        }
    }
}

typedef CUresult (*EncodeTiledFn)(
    CUtensorMap*, CUtensorMapDataType, cuuint32_t, void*,
    const cuuint64_t*, const cuuint64_t*, const cuuint32_t*, const cuuint32_t*,
    CUtensorMapInterleave, CUtensorMapSwizzle, CUtensorMapL2promotion,
    CUtensorMapFloatOOBfill);

extern "C" void kernel_launch(void* const* d_in, const int* in_sizes, int n_in,
                              void* d_out, int out_size) {
    const float* x = (const float*)d_in[0];
    const int* lid = (const int*)d_in[1];
    const float* W = (const float*)d_in[2];
    const float* Wd = (const float*)d_in[3];
    const float* Wu = (const float*)d_in[4];
    float* out = (float*)d_out;

    void* fp = nullptr;
    cudaDriverEntryPointQueryResult qr;
    cudaGetDriverEntryPoint("cuTensorMapEncodeTiled", &fp, cudaEnableDefault, &qr);
    EncodeTiledFn enc = (EncodeTiledFn)fp;
    CUtensorMap tmap;
    cuuint64_t dims[2] = {(cuuint64_t)K_TOTAL, 65536ull};
    cuuint64_t strides[1] = {(cuuint64_t)K_TOTAL * 4};
    cuuint32_t box[2] = {32, 128};
    cuuint32_t es[2] = {1, 1};
    enc(&tmap, CU_TENSOR_MAP_DATA_TYPE_FLOAT32, 2, (void*)x,
        dims, strides, box, es,
        CU_TENSOR_MAP_INTERLEAVE_NONE, CU_TENSOR_MAP_SWIZZLE_128B,
        CU_TENSOR_MAP_L2_PROMOTION_L2_128B, CU_TENSOR_MAP_FLOAT_OOB_FILL_NONE);

    cudaFuncSetAttribute(lora_gemm, cudaFuncAttributeMaxDynamicSharedMemorySize, SMEM_BYTES);
    int total = N_TOTAL * K_TOTAL + 50 * K_TOTAL * 8;
    prep_kernel<<<(total + 255) / 256, 256>>>(W, Wd);
    lora_gemm<<<GRID, THREADS, SMEM_BYTES>>>(tmap, lid, Wu, out);
}

// round 17
// speedup vs baseline: 1.1584x; 1.0065x over previous
#include <cuda_runtime.h>
#include <cuda.h>
#include <cstdint>

static constexpr int K_TOTAL = 1280, N_TOTAL = 1280;
static constexpr int BM = 128, BN = 256;
static constexpr int SLICES = 40;
static constexpr int NTILES = 5;
static constexpr int TILES = 2560;
static constexpr int GRIDC = 152;
static constexpr int THREADS = 512;
static constexpr int STAGES = 4;

static constexpr int A_STG = 16384;   // 128 rows * 128B, SW128 (TMA tile)
static constexpr int B_STG = 32768;
static constexpr int B2_STG = 1024;
static constexpr int OFF_A = 0;
static constexpr int OFF_B = 65536;
static constexpr int OFF_B2 = 196608;
static constexpr int OFF_WU = 200704;
static constexpr int OFF_DN = 204800;
static constexpr int OFF_BAR = 212992;
static constexpr int SMEM_BYTES = 213504;
static constexpr unsigned TX_BYTES = 16384u + 32768u + 1024u;

// W fragments, per 32-k slice block of 8192 floats:
// (((pair*4+ks)*32 + gid*4 + tig)*4 + nfo*2 + kh), pair = n16-group 0..15
__device__ __align__(16) float g_Wfrag[NTILES * SLICES * 8192];
// Wd fragments: [lora][slice32][(ks*32+lane)*2 + kh]
__device__ __align__(16) float g_Wdfrag[50 * SLICES * 256];

__device__ __forceinline__ uint32_t smem_u32(const void* p) {
    uint32_t a;
    asm("{ .reg .u64 t; cvta.to.shared.u64 t, %1; cvt.u32.u64 %0, t; }" : "=r"(a) : "l"(p));
    return a;
}
__device__ __forceinline__ uint32_t rna(float f) {
    uint32_t b;
    asm("cvt.rna.tf32.f32 %0, %1;" : "=r"(b) : "f"(f));
    return b;
}
__device__ __forceinline__ void mma8(float* c, const uint32_t* a, uint32_t b0, uint32_t b1) {
    asm volatile(
        "mma.sync.aligned.m16n8k8.row.col.f32.tf32.tf32.f32 "
        "{%0,%1,%2,%3}, {%4,%5,%6,%7}, {%8,%9}, {%0,%1,%2,%3};"
        : "+f"(c[0]), "+f"(c[1]), "+f"(c[2]), "+f"(c[3])
        : "r"(a[0]), "r"(a[1]), "r"(a[2]), "r"(a[3]), "r"(b0), "r"(b1));
}
__device__ __forceinline__ void bulk_cp(uint32_t dst, const void* src, uint32_t bytes, uint32_t mb) {
    asm volatile(
        "cp.async.bulk.shared::cta.global.mbarrier::complete_tx::bytes [%0], [%1], %2, [%3];"
        :: "r"(dst), "l"(src), "r"(bytes), "r"(mb) : "memory");
}
#define CP16(d, s) asm volatile("cp.async.cg.shared.global [%0], [%1], 16;" :: "r"(d), "l"(s))
#define CP_COMMIT() asm volatile("cp.async.commit_group;")
#define CP_WAIT0()  asm volatile("cp.async.wait_group 0;" ::: "memory")
#define MBAR_INIT(a, c) \
    asm volatile("mbarrier.init.shared.b64 [%0], %1;" :: "r"((uint32_t)(a)), "r"((uint32_t)(c)) : "memory")
#define MBAR_EXPECT(a, tx) \
    asm volatile("mbarrier.arrive.expect_tx.shared.b64 _, [%0], %1;" :: "r"((uint32_t)(a)), "r"((uint32_t)(tx)) : "memory")
#define MBAR_WAIT(a, ph) do { \
    uint32_t _m = (uint32_t)(a), _p = (uint32_t)(ph), _d; \
    asm volatile("{ .reg .pred p; mbarrier.try_wait.parity.acquire.cta.shared::cta.b64 p, [%1], %2; selp.b32 %0, 1, 0, p; }" \
        : "=r"(_d) : "r"(_m), "r"(_p) : "memory"); \
    if (!_d) { \
        asm volatile("{ .reg .pred P1;\nWL_%=: mbarrier.try_wait.parity.acquire.cta.shared::cta.b64 P1, [%0], %1, 0x989680;\n@P1 bra.uni WD_%=;\nbra.uni WL_%=;\nWD_%=: }" \
            :: "r"(_m), "r"(_p) : "memory"); \
    } \
} while (0)

// ---------------- prepass (unchanged fragment convention)
__global__ void prep_kernel(const float* __restrict__ W, const float* __restrict__ Wd) {
    int i = blockIdx.x * blockDim.x + threadIdx.x;
    const int NW = N_TOTAL * K_TOTAL;
    if (i < NW) {
        int n = i / K_TOTAL, k = i % K_TOTAL;
        int ntile = n >> 8, nn = n & 255;
        int pair = nn >> 4, nfo = (nn >> 3) & 1, gid = nn & 7;
        int slice = k >> 5, ks = (k >> 3) & 3, kh = (k >> 2) & 1, tig = k & 3;
        int off = (ntile * SLICES + slice) * 8192 +
                  (((pair * 4 + ks) * 32 + gid * 4 + tig) * 4 + nfo * 2 + kh);
        g_Wfrag[off] = __uint_as_float(rna(W[i]));
    } else if (i < NW + 50 * K_TOTAL * 8) {
        int j = i - NW;
        int gid = j & 7, t = j >> 3, k = t % K_TOTAL, l = t / K_TOTAL;
        float v = 0.f;
        if (gid < 4) v = __uint_as_float(rna(Wd[(l * 4 + gid) * K_TOTAL + k]));
        int slice = k >> 5, ks = (k >> 3) & 3, kh = (k >> 2) & 1, tig = k & 3;
        g_Wdfrag[(l * SLICES + slice) * 256 + (ks * 32 + gid * 4 + tig) * 2 + kh] = v;
    }
}

// ---------------- persistent fused kernel: continuous TMA pipeline
__global__ void __launch_bounds__(THREADS, 1)
lora_gemm(const __grid_constant__ CUtensorMap tmap,
          const int* __restrict__ lora_id,
          const float* __restrict__ Wu, float* __restrict__ out) {
    extern __shared__ char smem[];
    const uint32_t sb = smem_u32(smem);
    const int tid = threadIdx.x, lane = tid & 31, wid = tid >> 5;
    const int bid = blockIdx.x;

    const int gid = lane >> 2, tig = lane & 3;
    const int wr = wid >> 3, wc = wid & 7;

    const uint32_t abase0 = sb + OFF_A + (wr * 64 + (lane & 15)) * 128;
    const uint32_t hi16 = (lane >> 4) << 4;
    const uint32_t sxor = (lane & 7) << 4;
    const uint32_t bcons = sb + OFF_B + wc * 4096 + (lane << 4);
    const uint32_t b2cons = sb + OFF_B2 + (wc & 3) * 256 + lane * 8;

    const int total = (TILES - 1 - bid) / GRIDC + 1;
    const int S = total * SLICES;

    if (tid == 0) {
        #pragma unroll
        for (int st = 0; st < STAGES; ++st) MBAR_INIT(sb + OFF_BAR + 8 * st, 1);
    }
    __syncthreads();

    // ---- issue cursor: lives only in tid0's branch
    int gi = 0, i_s = 0, i_t = 0;
    int m0i = 0;
    const float* wsi = nullptr;
    const float* wdi = nullptr;
    if (tid == 0) {
        int t = bid;
        m0i = (t / NTILES) * BM;
        wsi = g_Wfrag + (size_t)(t % NTILES) * SLICES * 8192;
        int id2 = lora_id[m0i >> 12];
        int ix2 = (id2 >= 0) ? ((id2 >> 2) > 49 ? 49 : (id2 >> 2)) : 0;
        wdi = g_Wdfrag + (size_t)ix2 * SLICES * 256;
    }

    auto issue_one = [&]() {
        if (tid == 0 && gi < S) {
            const int st = gi & 3;
            const uint32_t mb = sb + OFF_BAR + 8 * st;
            MBAR_EXPECT(mb, TX_BYTES);
            asm volatile(
                "cp.async.bulk.tensor.2d.shared::cta.global.tile.mbarrier::complete_tx::bytes "
                "[%0], [%1, {%2, %3}], [%4];"
                :: "r"(sb + OFF_A + st * A_STG), "l"(&tmap),
                   "r"(i_s * 32), "r"(m0i), "r"(mb) : "memory");
            bulk_cp(sb + OFF_B + st * B_STG, wsi + (size_t)i_s * 8192, 32768, mb);
            bulk_cp(sb + OFF_B2 + st * B2_STG, wdi + i_s * 256, 1024, mb);
            ++gi;
            if (++i_s == SLICES) {
                i_s = 0;
                ++i_t;
                int t = bid + i_t * GRIDC;
                if (t < TILES) {
                    m0i = (t / NTILES) * BM;
                    wsi = g_Wfrag + (size_t)(t % NTILES) * SLICES * 8192;
                    int id2 = lora_id[m0i >> 12];
                    int ix2 = (id2 >= 0) ? ((id2 >> 2) > 49 ? 49 : (id2 >> 2)) : 0;
                    wdi = g_Wdfrag + (size_t)ix2 * SLICES * 256;
                }
            }
        } else if (tid == 0) {
            ++gi;
        }
    };
    issue_one(); issue_one(); issue_one(); issue_one();

    int ci = 0;
    #pragma unroll 1
    for (int ti = 0; ti < total; ++ti) {
        const int t = bid + ti * GRIDC;
        const int nt = t % NTILES, mt = t / NTILES;
        const int m0 = mt * BM, nbv = nt * BN;
        const int idv = lora_id[m0 >> 12];
        const int idxv = (idv >= 0) ? ((idv >> 2) > 49 ? 49 : (idv >> 2)) : 0;
        const float coeff = (idv >= 0) ? 1.f : 0.f;

        // prefetch this tile's Wu into smem (consumed in this tile's epilogue)
        if (tid < 256)
            CP16(sb + OFF_WU + tid * 16,
                 (const float*)((const float4*)Wu + (size_t)idxv * N_TOTAL + nbv + tid));
        CP_COMMIT();

        float acc[4][4][4];
        float accL[4][4];
        #pragma unroll
        for (int a = 0; a < 4; ++a) {
            #pragma unroll
            for (int b = 0; b < 4; ++b)
                acc[a][b][0] = acc[a][b][1] = acc[a][b][2] = acc[a][b][3] = 0.f;
            accL[a][0] = accL[a][1] = accL[a][2] = accL[a][3] = 0.f;
        }

        #pragma unroll 1
        for (int s = 0; s < SLICES; s += 2) {
            #pragma unroll
            for (int half = 0; half < 2; ++half) {
                const int c = ci + half;
                const int st = c & 3;
                MBAR_WAIT(sb + OFF_BAR + 8 * st, (c >> 2) & 1);
                const uint32_t ab = abase0 + st * A_STG;
                const uint32_t bb = bcons + st * B_STG;
                #pragma unroll
                for (int ksl = 0; ksl < 4; ++ksl) {
                    const uint32_t aoff = ((uint32_t)(ksl << 5) | hi16) ^ sxor;
                    uint32_t a[4][4];
                    #pragma unroll
                    for (int mf = 0; mf < 4; ++mf)
                        asm volatile("ldmatrix.sync.aligned.m8n8.x4.shared.b16 {%0,%1,%2,%3}, [%4];"
                                     : "=r"(a[mf][0]), "=r"(a[mf][1]), "=r"(a[mf][2]), "=r"(a[mf][3])
                                     : "r"(ab + mf * 2048 + aoff));
                    #pragma unroll
                    for (int nfp = 0; nfp < 2; ++nfp) {
                        uint32_t b[4];
                        asm volatile("ld.shared.v4.b32 {%0,%1,%2,%3}, [%4];"
                                     : "=r"(b[0]), "=r"(b[1]), "=r"(b[2]), "=r"(b[3])
                                     : "r"(bb + (((nfp * 4 + ksl) * 32) << 4)));
                        #pragma unroll
                        for (int mf = 0; mf < 4; ++mf) {
                            mma8(acc[mf][2 * nfp], a[mf], b[0], b[1]);
                            mma8(acc[mf][2 * nfp + 1], a[mf], b[2], b[3]);
                        }
                    }
                    if ((wc & 3) == ksl && wc < 4) {
                        uint32_t bl[2];
                        asm volatile("ld.shared.v2.b32 {%0,%1}, [%2];"
                                     : "=r"(bl[0]), "=r"(bl[1]) : "r"(b2cons + st * B2_STG));
                        #pragma unroll
                        for (int mf = 0; mf < 4; ++mf) mma8(accL[mf], a[mf], bl[0], bl[1]);
                    }
                }
            }
            ci += 2;
            __syncthreads();
            issue_one();
            issue_one();
        }

        // ---- epilogue (next-tile copies already in flight)
        CP_WAIT0();   // Wu prefetch done (issuing threads); visible after sync below
        float* dns = (float*)(smem + OFF_DN);
        if (wc < 4 && tig < 2) {
            float* db = dns + wc * 512;
            #pragma unroll
            for (int mf = 0; mf < 4; ++mf) {
                int mlo = wr * 64 + mf * 16 + gid, mhi = mlo + 8;
                db[mlo * 4 + 2 * tig] = accL[mf][0] * coeff;
                db[mlo * 4 + 2 * tig + 1] = accL[mf][1] * coeff;
                db[mhi * 4 + 2 * tig] = accL[mf][2] * coeff;
                db[mhi * 4 + 2 * tig + 1] = accL[mf][3] * coeff;
            }
        }
        __syncthreads();

        const float4* wus = (const float4*)(smem + OFF_WU);
        const float4* d0 = (const float4*)(dns);
        const float4* d1 = (const float4*)(dns + 512);
        const float4* d2 = (const float4*)(dns + 1024);
        const float4* d3 = (const float4*)(dns + 1536);
        #pragma unroll
        for (int mf = 0; mf < 4; ++mf) {
            int mlo = wr * 64 + mf * 16 + gid, mhi = mlo + 8;
            float4 a0 = d0[mlo], a1 = d1[mlo], a2 = d2[mlo], a3 = d3[mlo];
            float4 dlo = make_float4(a0.x + a1.x + a2.x + a3.x, a0.y + a1.y + a2.y + a3.y,
                                     a0.z + a1.z + a2.z + a3.z, a0.w + a1.w + a2.w + a3.w);
            float4 b0 = d0[mhi], b1 = d1[mhi], b2 = d2[mhi], b3 = d3[mhi];
            float4 dhi = make_float4(b0.x + b1.x + b2.x + b3.x, b0.y + b1.y + b2.y + b3.y,
                                     b0.z + b1.z + b2.z + b3.z, b0.w + b1.w + b2.w + b3.w);
            float* olo = out + (size_t)(m0 + mlo) * N_TOTAL + nbv;
            float* ohi = out + (size_t)(m0 + mhi) * N_TOTAL + nbv;
            #pragma unroll
            for (int nf = 0; nf < 4; ++nf) {
                int n = wc * 32 + nf * 8 + 2 * tig;
                float4 w0 = wus[n], w1 = wus[n + 1];
                float2 vlo, vhi;
                vlo.x = acc[mf][nf][0] + dlo.x * w0.x + dlo.y * w0.y + dlo.z * w0.z + dlo.w * w0.w;
                vlo.y = acc[mf][nf][1] + dlo.x * w1.x + dlo.y * w1.y + dlo.z * w1.z + dlo.w * w1.w;
                vhi.x = acc[mf][nf][2] + dhi.x * w0.x + dhi.y * w0.y + dhi.z * w0.z + dhi.w * w0.w;
                vhi.y = acc[mf][nf][3] + dhi.x * w1.x + dhi.y * w1.y + dhi.z * w1.z + dhi.w * w1.w;
                *(float2*)(olo + n) = vlo;
                *(float2*)(ohi + n) = vhi;
            }
        }
        __syncthreads();   // protect WU/DN before next tile's writes
    }
}

typedef CUresult (*EncodeTiledFn)(
    CUtensorMap*, CUtensorMapDataType, cuuint32_t, void*,
    const cuuint64_t*, const cuuint64_t*, const cuuint32_t*, const cuuint32_t*,
    CUtensorMapInterleave, CUtensorMapSwizzle, CUtensorMapL2promotion,
    CUtensorMapFloatOOBfill);

extern "C" void kernel_launch(void* const* d_in, const int* in_sizes, int n_in,
                              void* d_out, int out_size) {
    const float* x = (const float*)d_in[0];
    const int* lid = (const int*)d_in[1];
    const float* W = (const float*)d_in[2];
    const float* Wd = (const float*)d_in[3];
    const float* Wu = (const float*)d_in[4];
    float* out = (float*)d_out;

    void* fp = nullptr;
    cudaDriverEntryPointQueryResult qr;
    cudaGetDriverEntryPoint("cuTensorMapEncodeTiled", &fp, cudaEnableDefault, &qr);
    EncodeTiledFn enc = (EncodeTiledFn)fp;
    CUtensorMap tmap;
    cuuint64_t dims[2] = {(cuuint64_t)K_TOTAL, 65536ull};
    cuuint64_t strides[1] = {(cuuint64_t)K_TOTAL * 4};
    cuuint32_t box[2] = {32, 128};
    cuuint32_t es[2] = {1, 1};
    enc(&tmap, CU_TENSOR_MAP_DATA_TYPE_FLOAT32, 2, (void*)x,
        dims, strides, box, es,
        CU_TENSOR_MAP_INTERLEAVE_NONE, CU_TENSOR_MAP_SWIZZLE_128B,
        CU_TENSOR_MAP_L2_PROMOTION_L2_128B, CU_TENSOR_MAP_FLOAT_OOB_FILL_NONE);

    cudaFuncSetAttribute(lora_gemm, cudaFuncAttributeMaxDynamicSharedMemorySize, SMEM_BYTES);
    int total = N_TOTAL * K_TOTAL + 50 * K_TOTAL * 8;
    prep_kernel<<<(total + 255) / 256, 256>>>(W, Wd);
    lora_gemm<<<GRIDC, THREADS, SMEM_BYTES>>>(tmap, lid, Wu, out);
}